// round 13
// baseline (speedup 1.0000x reference)
#include <cuda_runtime.h>

#define NBINS   256
#define TPB     1024                      // 32 warps
#define KQ      2                         // quads held in registers per thread
#define NSLOT   32                        // slot spreading for the global flush
#define NBLOCKS 148
#define J_BYTES (NBINS * NBINS * 2)       // 128 KB joint histogram (u16 cells)
#define CQ      14                        // spill-path: 57344 px/CTA/chunk < 65536

__device__ int   g_slots[2][NSLOT][NBINS];   // zero-init; re-zeroed in final reset
__device__ float g_pxmap[NBINS];
__device__ int   g_done0;
__device__ int   g_done1;
__device__ volatile int g_release;

extern __shared__ unsigned int s_J[];     // dynamic: J as u32 words (2 u16 cells)

__device__ __forceinline__ int bin_of(float x) {
    return min(max((int)(x * 256.0f), 0), NBINS - 1);
}

// One joint-histogram increment: cell (b, c) -> word b*128 + (c>>1), half c&1.
__device__ __forceinline__ void jinc(int b, int c) {
    atomicAdd(&s_J[(b << 7) + (c >> 1)], 1u << ((c & 1) << 4));
}

// Branchless per-pixel interpolate on the fixed fs grid + clip + rescale-back.
__device__ __forceinline__ float apply1(float x,
                                        const float* __restrict__ fsv,
                                        const float* __restrict__ As,
                                        const float* __restrict__ Bs,
                                        float pm0, float pm255,
                                        float fs0, float fs255) {
    int j = (int)(x * 255.0f) + 1;
    j = min(max(j, 1), NBINS - 1);
    if (fsv[j - 1] > x) --j;          // index guess off by at most 1
    j = max(j, 1);
    if (fsv[j] <= x) ++j;
    j = min(j, NBINS - 1);
    float r = fmaf(As[j], x, Bs[j]);
    if (x <= fs0)   r = pm0;
    if (x >= fs255) r = pm255;
    r = fminf(fmaxf(r, 0.0f), 1.0f);
    return fmaf(r, 255.0f / 127.0f, -1.0f);
}

__global__ void __launch_bounds__(TPB, 1) k_fused(const float* __restrict__ src,
                                                  const float* __restrict__ tgt,
                                                  float* __restrict__ out, int n) {
    __shared__ int   sha[NBINS], shb[NBINS];
    __shared__ float fsv[NBINS], pmS[NBINS], As[NBINS], Bs[NBINS];
    __shared__ int   is_last;

    const int t    = threadIdx.x;
    const int nth  = gridDim.x * TPB;
    const int gtid = blockIdx.x * TPB + t;
    const int nq   = n >> 2;
    const float SC = 127.0f / 255.0f;

    if (t < NBINS) {
        sha[t] = 0;
        shb[t] = 0;
        // floating_space: np.arange semantics (f64 i*step -> f32), clipped
        float v = (float)((double)t * (1.0 / 255.0));
        fsv[t] = fminf(fmaxf(v, 0.0f), 1.0f);
    }

    const float4* s4 = (const float4*)src;
    const float4* t4 = (const float4*)tgt;
    float4*       o4 = (float4*)out;

    // cached path: whole image fits in register cache AND per-CTA px < 65536
    const bool cached = (nq <= KQ * nth);

    float xr[4 * KQ];

    if (cached) {
        // zero J (32768 u32): 8 uint4 per thread
        {
            uint4* z = (uint4*)s_J;
            #pragma unroll
            for (int i = 0; i < (NBINS * NBINS / 2 / 4) / TPB; ++i)
                z[t + i * TPB] = make_uint4(0, 0, 0, 0);
        }
        __syncthreads();

        #pragma unroll
        for (int k = 0; k < KQ; ++k) {
            int q = gtid + k * nth;
            if (q < nq) {
                float4 a  = s4[3 * q + 0];
                float4 b  = s4[3 * q + 1];
                float4 c  = s4[3 * q + 2];
                float4 ta = t4[3 * q + 0];
                float4 tb = t4[3 * q + 1];
                float4 tc = t4[3 * q + 2];

                float x0 = (a.x + 1.0f) * SC, x1 = (a.w + 1.0f) * SC;
                float x2 = (b.z + 1.0f) * SC, x3 = (c.y + 1.0f) * SC;
                xr[4 * k + 0] = x0; xr[4 * k + 1] = x1;
                xr[4 * k + 2] = x2; xr[4 * k + 3] = x3;

                float y0 = (ta.x + 1.0f) * SC * 0.299f + (ta.y + 1.0f) * SC * 0.587f + (ta.z + 1.0f) * SC * 0.114f;
                float y1 = (ta.w + 1.0f) * SC * 0.299f + (tb.x + 1.0f) * SC * 0.587f + (tb.y + 1.0f) * SC * 0.114f;
                float y2 = (tb.z + 1.0f) * SC * 0.299f + (tb.w + 1.0f) * SC * 0.587f + (tc.x + 1.0f) * SC * 0.114f;
                float y3 = (tc.y + 1.0f) * SC * 0.299f + (tc.z + 1.0f) * SC * 0.587f + (tc.w + 1.0f) * SC * 0.114f;

                // ONE atomic per pixel (joint histogram)
                jinc(bin_of(x0), bin_of(y0));
                jinc(bin_of(x1), bin_of(y1));
                jinc(bin_of(x2), bin_of(y2));
                jinc(bin_of(x3), bin_of(y3));
            }
        }
        __syncthreads();

        // ---- marginals: threads 0..255 rows (src), 256..511 cols (tgt) ----
        if (t < NBINS) {
            const int b = t;
            const unsigned int* row = s_J + (b << 7);
            unsigned int s = 0;
            #pragma unroll 8
            for (int i = 0; i < 128; ++i) {
                unsigned int w = row[(i + b) & 127];     // +b swizzle: no conflicts
                s += (w & 0xffffu) + (w >> 16);
            }
            sha[b] += (int)s;
        } else if (t < 2 * NBINS) {
            const int c = t - NBINS;
            const int widx = c >> 1;
            const int shft = (c & 1) << 4;
            unsigned int s = 0;
            #pragma unroll 8
            for (int b = 0; b < NBINS; ++b) {
                unsigned int w = s_J[(b << 7) + widx];   // broadcast pairs: no conflicts
                s += (w >> shft) & 0xffffu;
            }
            shb[c] += (int)s;
        }
        __syncthreads();
    } else {
        // general-n chunked path: x spilled to out
        const int CHUNK_Q = nth * CQ;
        for (int cbase = 0; cbase < nq; cbase += CHUNK_Q) {
            const int cend = min(cbase + CHUNK_Q, nq);
            {
                uint4* z = (uint4*)s_J;
                #pragma unroll
                for (int i = 0; i < (NBINS * NBINS / 2 / 4) / TPB; ++i)
                    z[t + i * TPB] = make_uint4(0, 0, 0, 0);
            }
            __syncthreads();
            for (int q = cbase + gtid; q < cend; q += nth) {
                float4 a  = s4[3 * q + 0];
                float4 b  = s4[3 * q + 1];
                float4 c  = s4[3 * q + 2];
                float4 ta = t4[3 * q + 0];
                float4 tb = t4[3 * q + 1];
                float4 tc = t4[3 * q + 2];
                float x0 = (a.x + 1.0f) * SC, x1 = (a.w + 1.0f) * SC;
                float x2 = (b.z + 1.0f) * SC, x3 = (c.y + 1.0f) * SC;
                o4[q] = make_float4(x0, x1, x2, x3);
                float y0 = (ta.x + 1.0f) * SC * 0.299f + (ta.y + 1.0f) * SC * 0.587f + (ta.z + 1.0f) * SC * 0.114f;
                float y1 = (ta.w + 1.0f) * SC * 0.299f + (tb.x + 1.0f) * SC * 0.587f + (tb.y + 1.0f) * SC * 0.114f;
                float y2 = (tb.z + 1.0f) * SC * 0.299f + (tb.w + 1.0f) * SC * 0.587f + (tc.x + 1.0f) * SC * 0.114f;
                float y3 = (tc.y + 1.0f) * SC * 0.299f + (tc.z + 1.0f) * SC * 0.587f + (tc.w + 1.0f) * SC * 0.114f;
                jinc(bin_of(x0), bin_of(y0));
                jinc(bin_of(x1), bin_of(y1));
                jinc(bin_of(x2), bin_of(y2));
                jinc(bin_of(x3), bin_of(y3));
            }
            __syncthreads();
            if (t < NBINS) {
                const int b = t;
                const unsigned int* row = s_J + (b << 7);
                unsigned int s = 0;
                #pragma unroll 8
                for (int i = 0; i < 128; ++i) {
                    unsigned int w = row[(i + b) & 127];
                    s += (w & 0xffffu) + (w >> 16);
                }
                sha[b] += (int)s;
            } else if (t < 2 * NBINS) {
                const int c = t - NBINS;
                const int widx = c >> 1;
                const int shft = (c & 1) << 4;
                unsigned int s = 0;
                #pragma unroll 8
                for (int b = 0; b < NBINS; ++b) {
                    unsigned int w = s_J[(b << 7) + widx];
                    s += (w >> shft) & 0xffffu;
                }
                shb[c] += (int)s;
            }
            __syncthreads();
        }
    }

    // Tail pixels (n % 4): at most 3, straight to global slots.
    float xtail = 0.0f;
    const int tidx = 4 * nq + gtid;
    if (tidx < n) {
        xtail = (src[3 * tidx] + 1.0f) * SC;
        atomicAdd(&g_slots[0][0][bin_of(xtail)], 1);
        float yr = (tgt[3 * tidx + 0] + 1.0f) * SC;
        float yg = (tgt[3 * tidx + 1] + 1.0f) * SC;
        float yb = (tgt[3 * tidx + 2] + 1.0f) * SC;
        atomicAdd(&g_slots[1][0][bin_of(yr * 0.299f + yg * 0.587f + yb * 0.114f)], 1);
    }

    // ---------------- Slotted flush (both marginals in parallel) ----------------
    {
        const int slot = blockIdx.x & (NSLOT - 1);
        if (t < NBINS) {
            int va = sha[t];
            if (va) atomicAdd(&g_slots[0][slot][t], va);
        } else if (t < 2 * NBINS) {
            int vb = shb[t - NBINS];
            if (vb) atomicAdd(&g_slots[1][slot][t - NBINS], vb);
        }
    }

    // Device-scope release of every thread's flush atomics.
    __threadfence();
    __syncthreads();

    // ---------------- Device-wide barrier ----------------
    if (t == 0) {
        int old = atomicAdd(&g_done0, 1);
        is_last = (old == (int)gridDim.x - 1);
    }
    __syncthreads();

    if (is_last) {
        // ---- reduce slots (coalesced, NO zeroing), CDF + pxmap ----
        __threadfence();   // acquire
        if (t < NBINS) {
            int suma = 0, sumb = 0;
            #pragma unroll
            for (int s = 0; s < NSLOT; ++s) {
                suma += *(volatile int*)&g_slots[0][s][t];
                sumb += *(volatile int*)&g_slots[1][s][t];
            }
            sha[t] = suma;
            shb[t] = sumb;
        }
        __syncthreads();
        #pragma unroll
        for (int off = 1; off < NBINS; off <<= 1) {
            int aself = 0, bself = 0, aprev = 0, bprev = 0;
            if (t < NBINS) {
                aself = sha[t]; bself = shb[t];
                if (t >= off) { aprev = sha[t - off]; bprev = shb[t - off]; }
            }
            __syncthreads();
            if (t < NBINS) { sha[t] = aself + aprev; shb[t] = bself + bprev; }
            __syncthreads();
        }
        if (t < NBINS) {
            int mint = shb[0];
            As[t] = (float)(shb[t] - mint) / (float)(n - 1);   // cdftgt
        }
        __syncthreads();
        if (t < NBINS) {
            int mins = sha[0];
            float x = (float)(sha[t] - mins) / (float)(n - 1); // cdfsrc
            // upper_bound on sorted cdftgt; edges overridden below
            int lo = 0, hi = NBINS - 1;
            while (lo < hi) { int mid = (lo + hi) >> 1; if (As[mid] > x) hi = mid; else lo = mid + 1; }
            int ind1 = lo;
            int ind0 = max(ind1 - 1, 0);
            float dx0 = As[ind0], dx1 = As[ind1];
            float dy0 = fsv[ind0], dy1 = fsv[ind1];
            float dnm = dx1 - dx0;
            float sd  = (dnm == 0.0f) ? 1.0f : dnm;
            float interp = dy0 + (dy1 - dy0) * (x - dx0) / sd;
            float res = (x <= As[0]) ? fsv[0]
                      : ((x >= As[NBINS - 1]) ? fsv[NBINS - 1] : interp);
            pmS[t] = res;
            g_pxmap[t] = res;
        }
        __threadfence();
        __syncthreads();
        if (t == 0) g_release = 1;
    } else {
        if (t == 0) {
            while (g_release == 0) __nanosleep(32);
            __threadfence();   // acquire
        }
        __syncthreads();
        if (t < NBINS) pmS[t] = __ldcg(&g_pxmap[t]);
    }
    __syncthreads();

    // ---- slope/intercept tables ----
    if (t > 0 && t < NBINS) {
        float d = fsv[t] - fsv[t - 1];          // strictly > 0
        float a = (pmS[t] - pmS[t - 1]) / d;
        As[t] = a;
        Bs[t] = pmS[t - 1] - a * fsv[t - 1];
    }
    __syncthreads();

    // ---------------- Phase 3: apply ----------------
    const float pm0 = pmS[0], pm255 = pmS[NBINS - 1];
    const float fs0 = fsv[0], fs255 = fsv[NBINS - 1];

    if (cached) {
        #pragma unroll
        for (int k = 0; k < KQ; ++k) {
            int q = gtid + k * nth;
            if (q < nq) {
                float4 v;
                v.x = apply1(xr[4 * k + 0], fsv, As, Bs, pm0, pm255, fs0, fs255);
                v.y = apply1(xr[4 * k + 1], fsv, As, Bs, pm0, pm255, fs0, fs255);
                v.z = apply1(xr[4 * k + 2], fsv, As, Bs, pm0, pm255, fs0, fs255);
                v.w = apply1(xr[4 * k + 3], fsv, As, Bs, pm0, pm255, fs0, fs255);
                o4[q] = v;
            }
        }
    } else {
        for (int q = gtid; q < nq; q += nth) {
            float4 v = o4[q];
            v.x = apply1(v.x, fsv, As, Bs, pm0, pm255, fs0, fs255);
            v.y = apply1(v.y, fsv, As, Bs, pm0, pm255, fs0, fs255);
            v.z = apply1(v.z, fsv, As, Bs, pm0, pm255, fs0, fs255);
            v.w = apply1(v.w, fsv, As, Bs, pm0, pm255, fs0, fs255);
            o4[q] = v;
        }
    }
    if (tidx < n) out[tidx] = apply1(xtail, fsv, As, Bs, pm0, pm255, fs0, fs255);

    // ---------------- Final reset (after ALL work device-wide) ----------------
    __syncthreads();
    if (t == 0) {
        __threadfence();
        int old = atomicAdd(&g_done1, 1);
        is_last = (old == (int)gridDim.x - 1);
    }
    __syncthreads();
    if (is_last) {
        // Every block passed g_done1 => every flush RED landed. Zero in parallel.
        int* gs = &g_slots[0][0][0];
        for (int i = t; i < 2 * NSLOT * NBINS; i += TPB) gs[i] = 0;
        __syncthreads();
        if (t == 0) {
            g_done0 = 0;
            g_done1 = 0;
            __threadfence();
            g_release = 0;
        }
    }
}

extern "C" void kernel_launch(void* const* d_in, const int* in_sizes, int n_in,
                              void* d_out, int out_size) {
    const float* src = (const float*)d_in[0];
    const float* tgt = (const float*)d_in[1];
    float* out = (float*)d_out;
    int n = in_sizes[0] / 3;   // H*W pixels

    cudaFuncSetAttribute(k_fused, cudaFuncAttributeMaxDynamicSharedMemorySize,
                         J_BYTES);

    k_fused<<<NBLOCKS, TPB, J_BYTES>>>(src, tgt, out, n);
}

// round 14
// speedup vs baseline: 1.0992x; 1.0992x over previous
#include <cuda_runtime.h>

#define NBINS   256
#define NSLOT   32
#define H_TPB   1024
#define H_BLK   148
#define J_BYTES (NBINS * NBINS * 2)      // 128 KB joint histogram (u16 cells)
#define CQ      14                       // px/CTA/chunk = 14*4*1024 = 57344 < 65536

__device__ int   g_slots[2][NSLOT][NBINS];   // zero-init; k2 re-zeroes after reading
__device__ float g_pxmap[NBINS];

extern __shared__ unsigned int s_J[];

__device__ __forceinline__ int bin_of(float x) {
    return min(max((int)(x * 256.0f), 0), NBINS - 1);
}

__device__ __forceinline__ void jinc(int b, int c) {
    atomicAdd(&s_J[(b << 7) + (c >> 1)], 1u << ((c & 1) << 4));
}

// ---------------------------------------------------------------------------
// k1: joint histogram + rescaled-x spill to out.
// ---------------------------------------------------------------------------
__global__ void __launch_bounds__(H_TPB, 1) k1_hist(const float* __restrict__ src,
                                                    const float* __restrict__ tgt,
                                                    float* __restrict__ out, int n) {
    __shared__ int sha[NBINS], shb[NBINS];

    const int t    = threadIdx.x;
    const int nth  = gridDim.x * H_TPB;
    const int gtid = blockIdx.x * H_TPB + t;
    const int nq   = n >> 2;
    const float SC = 127.0f / 255.0f;
    const int CHUNK_Q = nth * CQ;

    if (t < NBINS) { sha[t] = 0; shb[t] = 0; }

    const float4* s4 = (const float4*)src;
    const float4* t4 = (const float4*)tgt;
    float4*       o4 = (float4*)out;

    for (int cbase = 0; cbase < nq; cbase += CHUNK_Q) {
        const int cend = min(cbase + CHUNK_Q, nq);

        {   // zero J: 8 uint4 per thread
            uint4* z = (uint4*)s_J;
            #pragma unroll
            for (int i = 0; i < (NBINS * NBINS / 2 / 4) / H_TPB; ++i)
                z[t + i * H_TPB] = make_uint4(0, 0, 0, 0);
        }
        __syncthreads();

        #pragma unroll 2
        for (int q = cbase + gtid; q < cend; q += nth) {
            float4 a  = s4[3 * q + 0];
            float4 b  = s4[3 * q + 1];
            float4 c  = s4[3 * q + 2];
            float4 ta = t4[3 * q + 0];
            float4 tb = t4[3 * q + 1];
            float4 tc = t4[3 * q + 2];

            float x0 = (a.x + 1.0f) * SC, x1 = (a.w + 1.0f) * SC;
            float x2 = (b.z + 1.0f) * SC, x3 = (c.y + 1.0f) * SC;
            o4[q] = make_float4(x0, x1, x2, x3);

            float y0 = (ta.x + 1.0f) * SC * 0.299f + (ta.y + 1.0f) * SC * 0.587f + (ta.z + 1.0f) * SC * 0.114f;
            float y1 = (ta.w + 1.0f) * SC * 0.299f + (tb.x + 1.0f) * SC * 0.587f + (tb.y + 1.0f) * SC * 0.114f;
            float y2 = (tb.z + 1.0f) * SC * 0.299f + (tb.w + 1.0f) * SC * 0.587f + (tc.x + 1.0f) * SC * 0.114f;
            float y3 = (tc.y + 1.0f) * SC * 0.299f + (tc.z + 1.0f) * SC * 0.587f + (tc.w + 1.0f) * SC * 0.114f;

            jinc(bin_of(x0), bin_of(y0));       // ONE atomic per pixel
            jinc(bin_of(x1), bin_of(y1));
            jinc(bin_of(x2), bin_of(y2));
            jinc(bin_of(x3), bin_of(y3));
        }
        __syncthreads();

        // ---- marginals ----
        if (t < NBINS) {
            // src row sum: 128 words, +b swizzle -> conflict-free
            const unsigned int* row = s_J + (t << 7);
            unsigned int s = 0;
            #pragma unroll 8
            for (int i = 0; i < 128; ++i) {
                unsigned int w = row[(i + t) & 127];
                s += (w & 0xffffu) + (w >> 16);
            }
            sha[t] += (int)s;
        } else if (t < 3 * NBINS) {
            // tgt col sum: 512 threads, 2 per column (half the rows each)
            const int u    = t - NBINS;
            const int c    = u >> 1;
            const int half = u & 1;
            const int widx = c >> 1;
            const int shft = (c & 1) << 4;
            unsigned int s = 0;
            #pragma unroll 8
            for (int b = half * 128; b < half * 128 + 128; ++b) {
                unsigned int w = s_J[(b << 7) + widx];
                s += (w >> shft) & 0xffffu;
            }
            if (s) atomicAdd(&shb[c], (int)s);
        }
        __syncthreads();
    }

    // Tail pixels (n % 4): at most 3, straight to global slot 0.
    const int tidx = 4 * nq + gtid;
    if (tidx < n) {
        float x = (src[3 * tidx] + 1.0f) * SC;
        out[tidx] = x;
        atomicAdd(&g_slots[0][0][bin_of(x)], 1);
        float yr = (tgt[3 * tidx + 0] + 1.0f) * SC;
        float yg = (tgt[3 * tidx + 1] + 1.0f) * SC;
        float yb = (tgt[3 * tidx + 2] + 1.0f) * SC;
        atomicAdd(&g_slots[1][0][bin_of(yr * 0.299f + yg * 0.587f + yb * 0.114f)], 1);
    }

    // ---- slotted flush ----
    {
        const int slot = blockIdx.x & (NSLOT - 1);
        if (t < NBINS) {
            int va = sha[t];
            if (va) atomicAdd(&g_slots[0][slot][t], va);
        } else if (t < 2 * NBINS) {
            int vb = shb[t - NBINS];
            if (vb) atomicAdd(&g_slots[1][slot][t - NBINS], vb);
        }
    }
}

// ---------------------------------------------------------------------------
// k2: single block — reduce slots (and zero them), CDF, pxmap.
// ---------------------------------------------------------------------------
__global__ void k2_cdf(int n) {
    __shared__ int   sha[NBINS], shb[NBINS];
    __shared__ float fsv[NBINS], ct[NBINS];
    const int t = threadIdx.x;

    {   // floating_space: np.arange semantics (f64 i*step -> f32), clipped
        float v = (float)((double)t * (1.0 / 255.0));
        fsv[t] = fminf(fmaxf(v, 0.0f), 1.0f);
    }
    {
        int suma = 0, sumb = 0;
        #pragma unroll
        for (int s = 0; s < NSLOT; ++s) {
            suma += g_slots[0][s][t];
            sumb += g_slots[1][s][t];
            g_slots[0][s][t] = 0;           // safe: k1 fully done (kernel boundary)
            g_slots[1][s][t] = 0;
        }
        sha[t] = suma;
        shb[t] = sumb;
    }
    __syncthreads();
    #pragma unroll
    for (int off = 1; off < NBINS; off <<= 1) {
        int aself = sha[t], bself = shb[t];
        int aprev = (t >= off) ? sha[t - off] : 0;
        int bprev = (t >= off) ? shb[t - off] : 0;
        __syncthreads();
        sha[t] = aself + aprev;
        shb[t] = bself + bprev;
        __syncthreads();
    }
    {
        int mint = shb[0];
        ct[t] = (float)(shb[t] - mint) / (float)(n - 1);      // cdftgt
    }
    __syncthreads();
    {
        int mins = sha[0];
        float x = (float)(sha[t] - mins) / (float)(n - 1);    // cdfsrc
        // upper_bound on sorted cdftgt; edge cases overridden below
        int lo = 0, hi = NBINS - 1;
        while (lo < hi) { int mid = (lo + hi) >> 1; if (ct[mid] > x) hi = mid; else lo = mid + 1; }
        int ind1 = lo;
        int ind0 = max(ind1 - 1, 0);
        float dx0 = ct[ind0], dx1 = ct[ind1];
        float dy0 = fsv[ind0], dy1 = fsv[ind1];
        float dnm = dx1 - dx0;
        float sd  = (dnm == 0.0f) ? 1.0f : dnm;
        float interp = dy0 + (dy1 - dy0) * (x - dx0) / sd;
        float res = (x <= ct[0]) ? fsv[0]
                  : ((x >= ct[NBINS - 1]) ? fsv[NBINS - 1] : interp);
        g_pxmap[t] = res;
    }
}

// ---------------------------------------------------------------------------
// k3: per-pixel apply, in-place on out. blockDim 256.
// ---------------------------------------------------------------------------
__device__ __forceinline__ float apply1(float x,
                                        const float* __restrict__ fsv,
                                        const float* __restrict__ As,
                                        const float* __restrict__ Bs,
                                        float pm0, float pm255,
                                        float fs0, float fs255) {
    int j = (int)(x * 255.0f) + 1;
    j = min(max(j, 1), NBINS - 1);
    if (fsv[j - 1] > x) --j;
    j = max(j, 1);
    if (fsv[j] <= x) ++j;
    j = min(j, NBINS - 1);
    float r = fmaf(As[j], x, Bs[j]);
    if (x <= fs0)   r = pm0;
    if (x >= fs255) r = pm255;
    r = fminf(fmaxf(r, 0.0f), 1.0f);
    return fmaf(r, 255.0f / 127.0f, -1.0f);
}

__global__ void __launch_bounds__(256, 6) k3_apply(float* __restrict__ io, int n) {
    __shared__ float fsv[NBINS], pmS[NBINS], As[NBINS], Bs[NBINS];
    const int t = threadIdx.x;

    {
        float v = (float)((double)t * (1.0 / 255.0));
        fsv[t] = fminf(fmaxf(v, 0.0f), 1.0f);
        pmS[t] = g_pxmap[t];
    }
    __syncthreads();
    if (t > 0) {
        float d = fsv[t] - fsv[t - 1];
        float a = (pmS[t] - pmS[t - 1]) / d;
        As[t] = a;
        Bs[t] = pmS[t - 1] - a * fsv[t - 1];
    }
    __syncthreads();

    const float pm0 = pmS[0], pm255 = pmS[NBINS - 1];
    const float fs0 = fsv[0], fs255 = fsv[NBINS - 1];

    float4* io4 = (float4*)io;
    const int nq = n >> 2;
    const int stride = gridDim.x * blockDim.x;
    for (int q = blockIdx.x * blockDim.x + t; q < nq; q += stride) {
        float4 v = io4[q];
        v.x = apply1(v.x, fsv, As, Bs, pm0, pm255, fs0, fs255);
        v.y = apply1(v.y, fsv, As, Bs, pm0, pm255, fs0, fs255);
        v.z = apply1(v.z, fsv, As, Bs, pm0, pm255, fs0, fs255);
        v.w = apply1(v.w, fsv, As, Bs, pm0, pm255, fs0, fs255);
        io4[q] = v;
    }
    for (int i = 4 * nq + blockIdx.x * blockDim.x + t; i < n; i += stride)
        io[i] = apply1(io[i], fsv, As, Bs, pm0, pm255, fs0, fs255);
}

// ---------------------------------------------------------------------------
extern "C" void kernel_launch(void* const* d_in, const int* in_sizes, int n_in,
                              void* d_out, int out_size) {
    const float* src = (const float*)d_in[0];
    const float* tgt = (const float*)d_in[1];
    float* out = (float*)d_out;
    int n = in_sizes[0] / 3;   // H*W pixels
    int nq = n >> 2;

    cudaFuncSetAttribute(k1_hist, cudaFuncAttributeMaxDynamicSharedMemorySize,
                         J_BYTES);

    int ablocks = (nq + 255) / 256;
    if (ablocks > 888) ablocks = 888;
    if (ablocks < 1) ablocks = 1;

    k1_hist<<<H_BLK, H_TPB, J_BYTES>>>(src, tgt, out, n);
    k2_cdf<<<1, NBINS>>>(n);
    k3_apply<<<ablocks, 256>>>(out, n);
}